// round 6
// baseline (speedup 1.0000x reference)
#include <cuda_runtime.h>
#include <cstdint>

#define TASKS   128
#define NSAMP   2048
#define INDIM   256
#define OUTDIM  256
#define MAXITEMS 384          // Σ ceil(cnt/8) ≤ 128 + 2048/8
#define K2_CTAS  192          // 768 warps = 2 * MAXITEMS
#define WSTRIDE  2056         // floats per warp x-tile region (256*8 + pad for i=256 overread)

__device__ unsigned short g_slist[NSAMP];
__device__ int2 g_items[MAXITEMS];   // x = base | (scount<<12), y = task
__device__ int g_nitems;

__device__ __forceinline__ unsigned smem_u32(const void* p) {
    unsigned r;
    asm("{ .reg .u64 t; cvta.to.shared.u64 t, %1; cvt.u32.u64 %0, t; }" : "=r"(r) : "l"(p));
    return r;
}
__device__ __forceinline__ unsigned long long dup2(float f) {
    unsigned long long d; unsigned u = __float_as_uint(f);
    asm("mov.b64 %0, {%1, %1};" : "=l"(d) : "r"(u));
    return d;
}

// ---------------- K1: histogram + warp-shfl scans + worklist ----------------
__global__ __launch_bounds__(256) void k1_scan(const void* __restrict__ TIDS)
{
    __shared__ int cnts[TASKS], cursor[TASKS];
    __shared__ int soff[TASKS + 1], ioff[TASKS];
    __shared__ unsigned orv;

    const int tid = threadIdx.x;
    if (tid < TASKS) { cnts[tid] = 0; cursor[tid] = 0; }
    if (tid == 0) orv = 0;
    __syncthreads();

    const unsigned* w32 = (const unsigned*)TIDS;
    atomicOr(&orv, w32[4 * tid + 1] | w32[4 * tid + 3]);   // int64 iff hi-words all 0
    __syncthreads();
    const int shift = (orv == 0) ? 1 : 0;

    int myid[8];
    #pragma unroll
    for (int j = 0; j < 8; ++j) {
        const int n = tid + 256 * j;
        myid[j] = (int)w32[(unsigned)n << shift];
        atomicAdd(&cnts[myid[j]], 1);
    }
    __syncthreads();

    if (tid < 32) {                       // warp 0: both scans via shfl
        int c[4], pc[4], pi[4];
        int sc = 0, si = 0;
        #pragma unroll
        for (int j = 0; j < 4; ++j) {
            c[j] = cnts[tid * 4 + j];
            pc[j] = sc; sc += c[j];
            pi[j] = si; si += (c[j] + 7) >> 3;
        }
        int vc = sc, vi = si;
        #pragma unroll
        for (int d = 1; d < 32; d <<= 1) {
            int uc = __shfl_up_sync(0xffffffffu, vc, d);
            int ui = __shfl_up_sync(0xffffffffu, vi, d);
            if (tid >= d) { vc += uc; vi += ui; }
        }
        const int ec = vc - sc, ei = vi - si;   // exclusive
        #pragma unroll
        for (int j = 0; j < 4; ++j) {
            soff[tid * 4 + j] = ec + pc[j];
            ioff[tid * 4 + j] = ei + pi[j];
        }
        if (tid == 31) { soff[TASKS] = ec + sc; g_nitems = ei + si; }
    }
    __syncthreads();

    if (tid < TASKS) {
        const int b = soff[tid], cnt = soff[tid + 1] - b, io = ioff[tid];
        for (int g = 0; g * 8 < cnt; ++g) {
            int rem = cnt - g * 8; if (rem > 8) rem = 8;
            g_items[io + g] = make_int2((b + 8 * g) | (rem << 12), tid);
        }
    }
    #pragma unroll
    for (int j = 0; j < 8; ++j) {
        const int n = tid + 256 * j;
        const int t = myid[j];
        const int p = atomicAdd(&cursor[t], 1);
        g_slist[soff[t] + p] = (unsigned short)n;   // order in-task irrelevant: per-sample
    }                                               // i-reduction order is fixed -> deterministic
}

// ---------------- K2: one warp = one (8-sample group x 128-col half) ----------------
// Thread: 4 consecutive out-cols x 4 sample-pairs. x via broadcast LDS (dbl-buffered),
// W via LDG.128 with 8-deep rotating prefetch.
__device__ __forceinline__ void stage(float4& wb, const float4* __restrict__ Wp, bool pm,
                                      unsigned long long (&xu)[4], unsigned long long (&xl)[4],
                                      unsigned nextaddr, unsigned long long (&acc)[16])
{
    unsigned long long wd0 = dup2(wb.x), wd1 = dup2(wb.y), wd2 = dup2(wb.z), wd3 = dup2(wb.w);
    if (pm) wb = __ldg(Wp);                       // prefetch i+8
    asm("ld.shared.v2.b64 {%0,%1},[%2];" : "=l"(xl[0]), "=l"(xl[1]) : "r"(nextaddr));
    asm("ld.shared.v2.b64 {%0,%1},[%2];" : "=l"(xl[2]), "=l"(xl[3]) : "r"(nextaddr + 16));
    #define FF(o, p) asm("fma.rn.f32x2 %0, %1, %2, %0;" : "+l"(acc[(o)*4+(p)]) : "l"(xu[p]), "l"(wd##o));
    FF(0,0) FF(0,1) FF(0,2) FF(0,3)
    FF(1,0) FF(1,1) FF(1,2) FF(1,3)
    FF(2,0) FF(2,1) FF(2,2) FF(2,3)
    FF(3,0) FF(3,1) FF(3,2) FF(3,3)
    #undef FF
}

__global__ __launch_bounds__(128) void k2_gemm(const float* __restrict__ X,
                                               const float* __restrict__ W,
                                               float* __restrict__ OUT)
{
    __shared__ __align__(16) float xt[4 * WSTRIDE];
    const int tid = threadIdx.x, wid = tid >> 5, lane = tid & 31;
    const int gw = blockIdx.x * 4 + wid;
    const int item = gw >> 1, half = gw & 1;
    if (item >= g_nitems) return;

    const int2 it = g_items[item];
    const int base = it.x & 0xfff, scount = it.x >> 12, task = it.y;

    float* myxt = xt + wid * WSTRIDE;
    {   // transposed tile load: lane -> (s = lane&7, q = lane>>3), 16 LDG.128 each
        const int s = lane & 7, q = lane >> 3;
        const bool valid = (s < scount);
        const unsigned srow = valid ? (unsigned)g_slist[base + s] : 0u;
        const float4* row = (const float4*)(X + srow * INDIM);
        #pragma unroll
        for (int k = 0; k < 16; ++k) {
            const int iv = q + 4 * k;
            float4 v;
            if (valid) v = __ldg(row + iv);
            else       v = make_float4(0.f, 0.f, 0.f, 0.f);
            const int i = iv * 4;
            myxt[(i + 0) * 8 + s] = v.x;
            myxt[(i + 1) * 8 + s] = v.y;
            myxt[(i + 2) * 8 + s] = v.z;
            myxt[(i + 3) * 8 + s] = v.w;
        }
    }
    __syncwarp();

    const int o0 = half * 128 + lane * 4;
    const float4* W4 = (const float4*)(W + (size_t)task * INDIM * OUTDIM + o0); // +i*64 per row
    const unsigned xb = smem_u32(myxt);

    unsigned long long acc[16];
    #pragma unroll
    for (int k = 0; k < 16; ++k) acc[k] = 0ull;

    float4 wb0 = __ldg(W4 + 0 * 64), wb1 = __ldg(W4 + 1 * 64), wb2 = __ldg(W4 + 2 * 64),
           wb3 = __ldg(W4 + 3 * 64), wb4 = __ldg(W4 + 4 * 64), wb5 = __ldg(W4 + 5 * 64),
           wb6 = __ldg(W4 + 6 * 64), wb7 = __ldg(W4 + 7 * 64);

    unsigned long long xA[4], xB[4];
    asm("ld.shared.v2.b64 {%0,%1},[%2];" : "=l"(xA[0]), "=l"(xA[1]) : "r"(xb));
    asm("ld.shared.v2.b64 {%0,%1},[%2];" : "=l"(xA[2]), "=l"(xA[3]) : "r"(xb + 16));

    #pragma unroll 1
    for (int m = 0; m < 32; ++m) {                // 8 i-values per iteration
        const bool pm = (m < 31);
        const unsigned ib = xb + (unsigned)m * 256;            // i = 8m, 32B per row
        const float4* Wp = W4 + (size_t)(8 * m + 8) * 64;      // prefetch base (i+8)
        stage(wb0, Wp + 0 * 64, pm, xA, xB, ib + 1 * 32, acc);
        stage(wb1, Wp + 1 * 64, pm, xB, xA, ib + 2 * 32, acc);
        stage(wb2, Wp + 2 * 64, pm, xA, xB, ib + 3 * 32, acc);
        stage(wb3, Wp + 3 * 64, pm, xB, xA, ib + 4 * 32, acc);
        stage(wb4, Wp + 4 * 64, pm, xA, xB, ib + 5 * 32, acc);
        stage(wb5, Wp + 5 * 64, pm, xB, xA, ib + 6 * 32, acc);
        stage(wb6, Wp + 6 * 64, pm, xA, xB, ib + 7 * 32, acc);
        stage(wb7, Wp + 7 * 64, pm, xB, xA, ib + 8 * 32, acc); // m=31: reads pad (in-bounds)
    }

    #pragma unroll
    for (int p = 0; p < 4; ++p) {
        unsigned l0, h0, l1, h1, l2, h2, l3, h3;
        asm("mov.b64 {%0,%1},%2;" : "=r"(l0), "=r"(h0) : "l"(acc[0 * 4 + p]));
        asm("mov.b64 {%0,%1},%2;" : "=r"(l1), "=r"(h1) : "l"(acc[1 * 4 + p]));
        asm("mov.b64 {%0,%1},%2;" : "=r"(l2), "=r"(h2) : "l"(acc[2 * 4 + p]));
        asm("mov.b64 {%0,%1},%2;" : "=r"(l3), "=r"(h3) : "l"(acc[3 * 4 + p]));
        const int s0 = 2 * p, s1 = 2 * p + 1;
        if (s0 < scount) {
            const unsigned r = g_slist[base + s0];
            float4 v = make_float4(__uint_as_float(l0), __uint_as_float(l1),
                                   __uint_as_float(l2), __uint_as_float(l3));
            *(float4*)(OUT + (size_t)r * OUTDIM + o0) = v;
        }
        if (s1 < scount) {
            const unsigned r = g_slist[base + s1];
            float4 v = make_float4(__uint_as_float(h0), __uint_as_float(h1),
                                   __uint_as_float(h2), __uint_as_float(h3));
            *(float4*)(OUT + (size_t)r * OUTDIM + o0) = v;
        }
    }
}

extern "C" void kernel_launch(void* const* d_in, const int* in_sizes, int n_in,
                              void* d_out, int out_size)
{
    const float* X    = (const float*)d_in[0];
    const void*  TIDS = d_in[1];
    const float* W    = (const float*)d_in[2];
    float*       OUT  = (float*)d_out;

    k1_scan<<<1, 256>>>(TIDS);
    k2_gemm<<<K2_CTAS, 128>>>(X, W, OUT);
}

// round 7
// speedup vs baseline: 1.0756x; 1.0756x over previous
#include <cuda_runtime.h>
#include <cstdint>

#define TASKS    128
#define NSAMP    2048
#define INDIM    256
#define OUTDIM   256
#define TILE     16
#define MAXITEMS 256

__device__ unsigned short g_slist[NSAMP];
__device__ int2 g_items[MAXITEMS];   // x = base | (scount<<16), y = task
__device__ int g_nitems;

__device__ __forceinline__ unsigned smem_u32(const void* p) {
    unsigned r;
    asm("{ .reg .u64 t; cvta.to.shared.u64 t, %1; cvt.u32.u64 %0, t; }" : "=r"(r) : "l"(p));
    return r;
}
__device__ __forceinline__ unsigned long long dup2(float f) {
    unsigned long long d; unsigned u = __float_as_uint(f);
    asm("mov.b64 %0, {%1, %1};" : "=l"(d) : "r"(u));
    return d;
}

// ---------------- K1: histogram + warp-shfl scans + 16-sample-tile worklist ----------------
__global__ __launch_bounds__(256) void k1_scan(const void* __restrict__ TIDS)
{
    __shared__ int cnts[TASKS], cursor[TASKS];
    __shared__ int soff[TASKS + 1], ioff[TASKS];
    __shared__ unsigned orv;

    const int tid = threadIdx.x;
    if (tid < TASKS) { cnts[tid] = 0; cursor[tid] = 0; }
    if (tid == 0) orv = 0;
    __syncthreads();

    const unsigned* w32 = (const unsigned*)TIDS;
    atomicOr(&orv, w32[4 * tid + 1] | w32[4 * tid + 3]);   // int64 iff hi-words all 0
    __syncthreads();
    const int shift = (orv == 0) ? 1 : 0;

    int myid[8];
    #pragma unroll
    for (int j = 0; j < 8; ++j) {
        const int n = tid + 256 * j;
        myid[j] = (int)w32[(unsigned)n << shift];
        atomicAdd(&cnts[myid[j]], 1);
    }
    __syncthreads();

    if (tid < 32) {                       // warp 0: both prefix scans via shfl
        int c[4], pc[4], pi[4];
        int sc = 0, si = 0;
        #pragma unroll
        for (int j = 0; j < 4; ++j) {
            c[j] = cnts[tid * 4 + j];
            pc[j] = sc; sc += c[j];
            pi[j] = si; si += (c[j] + TILE - 1) >> 4;
        }
        int vc = sc, vi = si;
        #pragma unroll
        for (int d = 1; d < 32; d <<= 1) {
            int uc = __shfl_up_sync(0xffffffffu, vc, d);
            int ui = __shfl_up_sync(0xffffffffu, vi, d);
            if (tid >= d) { vc += uc; vi += ui; }
        }
        const int ec = vc - sc, ei = vi - si;
        #pragma unroll
        for (int j = 0; j < 4; ++j) {
            soff[tid * 4 + j] = ec + pc[j];
            ioff[tid * 4 + j] = ei + pi[j];
        }
        if (tid == 31) { soff[TASKS] = ec + sc; g_nitems = ei + si; }
    }
    __syncthreads();

    if (tid < TASKS) {
        const int b = soff[tid], cnt = soff[tid + 1] - b, io = ioff[tid];
        for (int g = 0; g * TILE < cnt; ++g) {
            int rem = cnt - g * TILE; if (rem > TILE) rem = TILE;
            g_items[io + g] = make_int2((b + TILE * g) | (rem << 16), tid);
        }
    }
    #pragma unroll
    for (int j = 0; j < 8; ++j) {
        const int n = tid + 256 * j;
        const int t = myid[j];
        const int p = atomicAdd(&cursor[t], 1);
        g_slist[soff[t] + p] = (unsigned short)n;   // in-task order irrelevant: per-sample
    }                                               // i-order fixed -> deterministic output
}

// ---------------- K2: CTA = one 16-sample x 256-col tile; thread = 2 cols x 16 samples --------
// x row (64B) broadcast-LDS double-buffered; W float2 per i with 8-deep rotating prefetch.
__device__ __forceinline__ void stage(float2& wb, const float2* __restrict__ Wp, bool pm,
                                      unsigned long long (&xu)[8], unsigned long long (&xl)[8],
                                      unsigned nextaddr, unsigned long long (&acc)[16])
{
    const unsigned long long wd0 = dup2(wb.x), wd1 = dup2(wb.y);
    if (pm) wb = __ldg(Wp);                           // prefetch W for i+8
    asm("ld.shared.v2.b64 {%0,%1},[%2];" : "=l"(xl[0]), "=l"(xl[1]) : "r"(nextaddr));
    asm("ld.shared.v2.b64 {%0,%1},[%2];" : "=l"(xl[2]), "=l"(xl[3]) : "r"(nextaddr + 16));
    asm("ld.shared.v2.b64 {%0,%1},[%2];" : "=l"(xl[4]), "=l"(xl[5]) : "r"(nextaddr + 32));
    asm("ld.shared.v2.b64 {%0,%1},[%2];" : "=l"(xl[6]), "=l"(xl[7]) : "r"(nextaddr + 48));
    #pragma unroll
    for (int p = 0; p < 8; ++p) {
        asm("fma.rn.f32x2 %0, %1, %2, %0;" : "+l"(acc[p])     : "l"(xu[p]), "l"(wd0));
        asm("fma.rn.f32x2 %0, %1, %2, %0;" : "+l"(acc[8 + p]) : "l"(xu[p]), "l"(wd1));
    }
}

__global__ __launch_bounds__(128) void k2_gemm(const float* __restrict__ X,
                                               const float* __restrict__ W,
                                               float* __restrict__ OUT)
{
    __shared__ __align__(16) float xt[INDIM * TILE + 16];   // +64B pad for last-stage overread
    __shared__ unsigned short sl[TILE];

    const int tid = threadIdx.x;
    const int item = blockIdx.x;
    if (item >= g_nitems) return;

    const int2 it = g_items[item];
    const int base = it.x & 0xffff, scount = it.x >> 16, task = it.y;

    if (tid < TILE) sl[tid] = (tid < scount) ? g_slist[base + tid] : (unsigned short)0;

    {   // transposed tile fill: thread -> (s = tid&15, q = tid>>4), 8 LDG.128 each
        const int s = tid & 15, q = tid >> 4;
        const bool valid = (s < scount);
        const float4* row = (const float4*)(X +
            (valid ? (unsigned)g_slist[base + s] * INDIM : 0u));
        #pragma unroll
        for (int k = 0; k < 8; ++k) {
            const int iv = q + 8 * k;
            float4 v;
            if (valid) v = __ldg(row + iv);
            else       v = make_float4(0.f, 0.f, 0.f, 0.f);
            const int i = iv * 4;
            xt[(i + 0) * TILE + s] = v.x;
            xt[(i + 1) * TILE + s] = v.y;
            xt[(i + 2) * TILE + s] = v.z;
            xt[(i + 3) * TILE + s] = v.w;
        }
    }
    __syncthreads();

    const float2* W2 = (const float2*)(W + (size_t)task * INDIM * OUTDIM) + tid;
    const unsigned xb = smem_u32(xt);

    unsigned long long acc[16];
    #pragma unroll
    for (int k = 0; k < 16; ++k) acc[k] = 0ull;

    float2 w0 = __ldg(W2 + 0 * 128), w1 = __ldg(W2 + 1 * 128), w2 = __ldg(W2 + 2 * 128),
           w3 = __ldg(W2 + 3 * 128), w4 = __ldg(W2 + 4 * 128), w5 = __ldg(W2 + 5 * 128),
           w6 = __ldg(W2 + 6 * 128), w7 = __ldg(W2 + 7 * 128);

    unsigned long long xA[8], xB[8];
    asm("ld.shared.v2.b64 {%0,%1},[%2];" : "=l"(xA[0]), "=l"(xA[1]) : "r"(xb));
    asm("ld.shared.v2.b64 {%0,%1},[%2];" : "=l"(xA[2]), "=l"(xA[3]) : "r"(xb + 16));
    asm("ld.shared.v2.b64 {%0,%1},[%2];" : "=l"(xA[4]), "=l"(xA[5]) : "r"(xb + 32));
    asm("ld.shared.v2.b64 {%0,%1},[%2];" : "=l"(xA[6]), "=l"(xA[7]) : "r"(xb + 48));

    #pragma unroll 1
    for (int m = 0; m < 32; ++m) {                 // 8 i-values per iteration
        const bool pm = (m < 31);
        const unsigned ib = xb + (unsigned)m * (8 * 64);       // row i = 8m, 64B/row
        const float2* Wp = W2 + (size_t)(8 * m + 8) * 128;     // prefetch base (i+8)
        stage(w0, Wp + 0 * 128, pm, xA, xB, ib + 1 * 64, acc);
        stage(w1, Wp + 1 * 128, pm, xB, xA, ib + 2 * 64, acc);
        stage(w2, Wp + 2 * 128, pm, xA, xB, ib + 3 * 64, acc);
        stage(w3, Wp + 3 * 128, pm, xB, xA, ib + 4 * 64, acc);
        stage(w4, Wp + 4 * 128, pm, xA, xB, ib + 5 * 64, acc);
        stage(w5, Wp + 5 * 128, pm, xB, xA, ib + 6 * 64, acc);
        stage(w6, Wp + 6 * 128, pm, xA, xB, ib + 7 * 64, acc);
        stage(w7, Wp + 7 * 128, pm, xB, xA, ib + 8 * 64, acc); // m=31: reads 64B pad
    }

    float* outp = OUT + 2 * tid;
    #pragma unroll
    for (int p = 0; p < 8; ++p) {
        unsigned e_lo, e_hi, o_lo, o_hi;
        asm("mov.b64 {%0,%1},%2;" : "=r"(e_lo), "=r"(e_hi) : "l"(acc[p]));
        asm("mov.b64 {%0,%1},%2;" : "=r"(o_lo), "=r"(o_hi) : "l"(acc[8 + p]));
        const int s0 = 2 * p, s1 = 2 * p + 1;
        if (s0 < scount) {
            const unsigned r = sl[s0];
            float2 v = make_float2(__uint_as_float(e_lo), __uint_as_float(o_lo));
            *(float2*)(outp + (size_t)r * OUTDIM) = v;
        }
        if (s1 < scount) {
            const unsigned r = sl[s1];
            float2 v = make_float2(__uint_as_float(e_hi), __uint_as_float(o_hi));
            *(float2*)(outp + (size_t)r * OUTDIM) = v;
        }
    }
}

extern "C" void kernel_launch(void* const* d_in, const int* in_sizes, int n_in,
                              void* d_out, int out_size)
{
    const float* X    = (const float*)d_in[0];
    const void*  TIDS = d_in[1];
    const float* W    = (const float*)d_in[2];
    float*       OUT  = (float*)d_out;

    k1_scan<<<1, 256>>>(TIDS);
    k2_gemm<<<MAXITEMS, 128>>>(X, W, OUT);
}

// round 8
// speedup vs baseline: 1.0910x; 1.0144x over previous
#include <cuda_runtime.h>
#include <cstdint>

#define TASKS    128
#define NSAMP    2048
#define INDIM    256
#define OUTDIM   256
#define GRP      8            // samples per work item
#define MAXITEMS 384          // sum ceil(cnt/8) <= 2048/8 + 128
#define K2_GRID  (2 * MAXITEMS)

__device__ unsigned short g_slist[NSAMP];
__device__ int2 g_items[MAXITEMS];   // x = base | (scount<<16), y = task
__device__ int g_nitems;

__device__ __forceinline__ unsigned smem_u32(const void* p) {
    unsigned r;
    asm("{ .reg .u64 t; cvta.to.shared.u64 t, %1; cvt.u32.u64 %0, t; }" : "=r"(r) : "l"(p));
    return r;
}
__device__ __forceinline__ unsigned long long dup2(float f) {
    unsigned long long d; unsigned u = __float_as_uint(f);
    asm("mov.b64 %0, {%1, %1};" : "=l"(d) : "r"(u));
    return d;
}

// ---------------- K1: histogram + warp-shfl scans + 8-sample-group worklist ----------------
__global__ __launch_bounds__(256) void k1_scan(const void* __restrict__ TIDS)
{
    __shared__ int cnts[TASKS], cursor[TASKS];
    __shared__ int soff[TASKS + 1], ioff[TASKS];
    __shared__ unsigned orv;

    const int tid = threadIdx.x;
    if (tid < TASKS) { cnts[tid] = 0; cursor[tid] = 0; }
    if (tid == 0) orv = 0;
    __syncthreads();

    const unsigned* w32 = (const unsigned*)TIDS;
    atomicOr(&orv, w32[4 * tid + 1] | w32[4 * tid + 3]);   // int64 iff hi-words all 0
    __syncthreads();
    const int shift = (orv == 0) ? 1 : 0;

    int myid[8];
    #pragma unroll
    for (int j = 0; j < 8; ++j) {
        const int n = tid + 256 * j;
        myid[j] = (int)w32[(unsigned)n << shift];
        atomicAdd(&cnts[myid[j]], 1);
    }
    __syncthreads();

    if (tid < 32) {                       // warp 0: both prefix scans via shfl
        int c[4], pc[4], pi[4];
        int sc = 0, si = 0;
        #pragma unroll
        for (int j = 0; j < 4; ++j) {
            c[j] = cnts[tid * 4 + j];
            pc[j] = sc; sc += c[j];
            pi[j] = si; si += (c[j] + GRP - 1) >> 3;
        }
        int vc = sc, vi = si;
        #pragma unroll
        for (int d = 1; d < 32; d <<= 1) {
            int uc = __shfl_up_sync(0xffffffffu, vc, d);
            int ui = __shfl_up_sync(0xffffffffu, vi, d);
            if (tid >= d) { vc += uc; vi += ui; }
        }
        const int ec = vc - sc, ei = vi - si;
        #pragma unroll
        for (int j = 0; j < 4; ++j) {
            soff[tid * 4 + j] = ec + pc[j];
            ioff[tid * 4 + j] = ei + pi[j];
        }
        if (tid == 31) { soff[TASKS] = ec + sc; g_nitems = ei + si; }
    }
    __syncthreads();

    if (tid < TASKS) {
        const int b = soff[tid], cnt = soff[tid + 1] - b, io = ioff[tid];
        for (int g = 0; g * GRP < cnt; ++g) {
            int rem = cnt - g * GRP; if (rem > GRP) rem = GRP;
            g_items[io + g] = make_int2((b + GRP * g) | (rem << 16), tid);
        }
    }
    #pragma unroll
    for (int j = 0; j < 8; ++j) {
        const int n = tid + 256 * j;
        const int t = myid[j];
        const int p = atomicAdd(&cursor[t], 1);
        g_slist[soff[t] + p] = (unsigned short)n;   // in-task order irrelevant: per-sample
    }                                               // i-order fixed -> deterministic output
}

// ---------------- K2: CTA = (8 samples x 128 cols); thread = 1 col x 8 samples ----------------
// x rows broadcast-LDS (double-buffered); W scalar per i with 16-deep rotating prefetch.
__device__ __forceinline__ void stage(float& w, const float* __restrict__ pf, bool pm,
                                      unsigned long long (&xu)[4], unsigned long long (&xl)[4],
                                      unsigned nextaddr, unsigned long long (&acc)[4])
{
    const unsigned long long wd = dup2(w);
    if (pm) w = __ldg(pf);                           // prefetch W for i+16
    asm("ld.shared.v2.b64 {%0,%1},[%2];" : "=l"(xl[0]), "=l"(xl[1]) : "r"(nextaddr));
    asm("ld.shared.v2.b64 {%0,%1},[%2];" : "=l"(xl[2]), "=l"(xl[3]) : "r"(nextaddr + 16));
    asm("fma.rn.f32x2 %0, %1, %2, %0;" : "+l"(acc[0]) : "l"(xu[0]), "l"(wd));
    asm("fma.rn.f32x2 %0, %1, %2, %0;" : "+l"(acc[1]) : "l"(xu[1]), "l"(wd));
    asm("fma.rn.f32x2 %0, %1, %2, %0;" : "+l"(acc[2]) : "l"(xu[2]), "l"(wd));
    asm("fma.rn.f32x2 %0, %1, %2, %0;" : "+l"(acc[3]) : "l"(xu[3]), "l"(wd));
}

__global__ __launch_bounds__(128) void k2_gemm(const float* __restrict__ X,
                                               const float* __restrict__ W,
                                               float* __restrict__ OUT)
{
    __shared__ __align__(16) float xt[INDIM * GRP + GRP];   // 8KB + 32B pad (last overread)
    __shared__ unsigned short sl[GRP];

    const int tid  = threadIdx.x;
    const int item = blockIdx.x >> 1;
    const int half = blockIdx.x & 1;
    if (item >= g_nitems) return;

    const int2 it = g_items[item];
    const int base = it.x & 0xffff, scount = it.x >> 16, task = it.y;

    if (tid < GRP) sl[tid] = (tid < scount) ? g_slist[base + tid] : (unsigned short)0;

    {   // transposed tile fill: thread -> (s = tid&7, q = tid>>3 in 0..15), 4 LDG.128 each
        const int s = tid & 7, q = tid >> 3;
        const bool valid = (s < scount);
        const float4* row = (const float4*)(X +
            (valid ? (unsigned)g_slist[base + s] * INDIM : 0u));
        #pragma unroll
        for (int k = 0; k < 4; ++k) {
            const int iv = q + 16 * k;
            float4 v;
            if (valid) v = __ldg(row + iv);
            else       v = make_float4(0.f, 0.f, 0.f, 0.f);
            const int i = iv * 4;
            xt[(i + 0) * GRP + s] = v.x;
            xt[(i + 1) * GRP + s] = v.y;
            xt[(i + 2) * GRP + s] = v.z;
            xt[(i + 3) * GRP + s] = v.w;
        }
    }
    __syncthreads();

    const int o = half * 128 + tid;
    const float* Wb = W + (size_t)task * INDIM * OUTDIM + o;   // + i*256 per row
    const unsigned xb = smem_u32(xt);

    unsigned long long acc[4];
    acc[0] = acc[1] = acc[2] = acc[3] = 0ull;

    float wA[8], wB[8];
    #pragma unroll
    for (int j = 0; j < 8; ++j) {
        wA[j] = __ldg(Wb + (size_t)j * OUTDIM);
        wB[j] = __ldg(Wb + (size_t)(8 + j) * OUTDIM);
    }

    unsigned long long x0[4], x1[4];
    asm("ld.shared.v2.b64 {%0,%1},[%2];" : "=l"(x0[0]), "=l"(x0[1]) : "r"(xb));
    asm("ld.shared.v2.b64 {%0,%1},[%2];" : "=l"(x0[2]), "=l"(x0[3]) : "r"(xb + 16));

    #pragma unroll 1
    for (int m = 0; m < 16; ++m) {                 // 16 i-values per iteration
        const bool pm = (m < 15);
        const unsigned ib = xb + (unsigned)m * (16 * 32);        // row i = 16m, 32B/row
        const float* Wp = Wb + (size_t)(16 * m + 16) * OUTDIM;   // prefetch base (i+16)
        stage(wA[0], Wp + 0 * OUTDIM, pm, x0, x1, ib + 1 * 32, acc);
        stage(wA[1], Wp + 1 * OUTDIM, pm, x1, x0, ib + 2 * 32, acc);
        stage(wA[2], Wp + 2 * OUTDIM, pm, x0, x1, ib + 3 * 32, acc);
        stage(wA[3], Wp + 3 * OUTDIM, pm, x1, x0, ib + 4 * 32, acc);
        stage(wA[4], Wp + 4 * OUTDIM, pm, x0, x1, ib + 5 * 32, acc);
        stage(wA[5], Wp + 5 * OUTDIM, pm, x1, x0, ib + 6 * 32, acc);
        stage(wA[6], Wp + 6 * OUTDIM, pm, x0, x1, ib + 7 * 32, acc);
        stage(wA[7], Wp + 7 * OUTDIM, pm, x1, x0, ib + 8 * 32, acc);
        stage(wB[0], Wp + 8 * OUTDIM, pm, x0, x1, ib + 9 * 32, acc);
        stage(wB[1], Wp + 9 * OUTDIM, pm, x1, x0, ib + 10 * 32, acc);
        stage(wB[2], Wp + 10 * OUTDIM, pm, x0, x1, ib + 11 * 32, acc);
        stage(wB[3], Wp + 11 * OUTDIM, pm, x1, x0, ib + 12 * 32, acc);
        stage(wB[4], Wp + 12 * OUTDIM, pm, x0, x1, ib + 13 * 32, acc);
        stage(wB[5], Wp + 13 * OUTDIM, pm, x1, x0, ib + 14 * 32, acc);
        stage(wB[6], Wp + 14 * OUTDIM, pm, x0, x1, ib + 15 * 32, acc);
        stage(wB[7], Wp + 15 * OUTDIM, pm, x1, x0, ib + 16 * 32, acc); // m=15: reads 32B pad
    }

    #pragma unroll
    for (int p = 0; p < 4; ++p) {
        unsigned lo, hi;
        asm("mov.b64 {%0,%1},%2;" : "=r"(lo), "=r"(hi) : "l"(acc[p]));
        const int s0 = 2 * p, s1 = 2 * p + 1;
        if (s0 < scount) OUT[(size_t)sl[s0] * OUTDIM + o] = __uint_as_float(lo);
        if (s1 < scount) OUT[(size_t)sl[s1] * OUTDIM + o] = __uint_as_float(hi);
    }
}

extern "C" void kernel_launch(void* const* d_in, const int* in_sizes, int n_in,
                              void* d_out, int out_size)
{
    const float* X    = (const float*)d_in[0];
    const void*  TIDS = d_in[1];
    const float* W    = (const float*)d_in[2];
    float*       OUT  = (float*)d_out;

    k1_scan<<<1, 256>>>(TIDS);
    k2_gemm<<<K2_GRID, 128>>>(X, W, OUT);
}